// round 7
// baseline (speedup 1.0000x reference)
#include <cuda_runtime.h>
#include <cuda_fp16.h>
#include <cstdint>

// Problem constants
#define B_   128
#define N_   4608
#define IL_  8
#define C_   10
#define L_   16
#define KDIM 160          // C_*L_
#define SROW (B_*KDIM)    // 20480

typedef unsigned long long u64t;

// packed f32x2 helpers (sm_103a FFMA2 path — PTX only, ptxas won't auto-fuse)
__device__ __forceinline__ u64t pk2(float lo, float hi) {
    u64t r; asm("mov.b64 %0,{%1,%2};" : "=l"(r) : "f"(lo), "f"(hi)); return r;
}
__device__ __forceinline__ void upk2(u64t v, float& lo, float& hi) {
    asm("mov.b64 {%0,%1},%2;" : "=f"(lo), "=f"(hi) : "l"(v));
}
__device__ __forceinline__ u64t ffma2(u64t a, u64t b, u64t c) {
    u64t d; asm("fma.rn.f32x2 %0,%1,%2,%3;" : "=l"(d) : "l"(a), "l"(b), "l"(c));
    return d;
}
__device__ __forceinline__ u64t fmul2(u64t a, u64t b) {
    u64t d; asm("mul.rn.f32x2 %0,%1,%2;" : "=l"(d) : "l"(a), "l"(b)); return d;
}
__device__ __forceinline__ u64t fadd2(u64t a, u64t b) {
    u64t d; asm("add.rn.f32x2 %0,%1,%2;" : "=l"(d) : "l"(a), "l"(b)); return d;
}

// Scratch (allocation-free rule: __device__ globals)
__device__ __half g_uh[(size_t)B_ * N_ * KDIM];   // 188 MB prediction tensor (fp16)
__device__ float  g_s[3][SROW];                   // s accumulators per round

// ---------------------------------------------------------------------------
// Zero the s accumulators (must happen every replay)
// ---------------------------------------------------------------------------
__global__ void k_zero() {
    int i = blockIdx.x * blockDim.x + threadIdx.x;
    if (i < 3 * SROW) ((float*)g_s)[i] = 0.0f;
}

// ---------------------------------------------------------------------------
// K1: u[b,n,k] = sum_j x[b,n,j] * W[n,j,k]  (fp32 via packed FFMA2, fp16
//     store) FUSED with s0[b,k] += 0.1 * sum_n u[b,n,k].
// grid (B/16, N/32), block 160 (thread = k).
// f32x2 lanes pair over batch; x tile in smem [nj][bp][j] read as
// ulonglong2 (LDS.128 broadcast, 2 j per load). Full fp32 accumulation ->
// u rounded to fp16 exactly once.
// ---------------------------------------------------------------------------
__global__ void __launch_bounds__(160) k_u_s0(const float* __restrict__ x,
                                              const float* __restrict__ W) {
    int b0 = blockIdx.x * 16;
    int n0 = blockIdx.y * 32;
    int k = threadIdx.x;
    __shared__ u64t xs2[32 * 8 * 8];   // 16 KB, [nj][bp][j], pair over batch

    for (int idx = k; idx < 16 * 32 * IL_; idx += 160) {
        int bi = idx >> 8, r = idx & 255;        // r = nj*8 + j (contig in gmem)
        int nj = r >> 3, j = r & 7;
        float val = x[(size_t)(b0 + bi) * (N_ * IL_) + (size_t)n0 * IL_ + r];
        ((float*)xs2)[((nj * 8 + (bi >> 1)) * 8 + j) * 2 + (bi & 1)] = val;
    }
    __syncthreads();

    u64t s0a[8];
#pragma unroll
    for (int i = 0; i < 8; i++) s0a[i] = pk2(0.f, 0.f);

    for (int nj = 0; nj < 32; nj++) {
        const float* Wn = W + (size_t)(n0 + nj) * (IL_ * KDIM);
        u64t w2[IL_];
#pragma unroll
        for (int j = 0; j < IL_; j++) {
            float w = Wn[j * KDIM + k];
            w2[j] = pk2(w, w);
        }
        __half* op = g_uh + ((size_t)b0 * N_ + (n0 + nj)) * KDIM + k;
        const ulonglong2* xp = (const ulonglong2*)&xs2[nj * 64];
#pragma unroll
        for (int bp = 0; bp < 8; bp++) {
            ulonglong2 x01 = xp[bp * 4 + 0];
            ulonglong2 x23 = xp[bp * 4 + 1];
            ulonglong2 x45 = xp[bp * 4 + 2];
            ulonglong2 x67 = xp[bp * 4 + 3];
            u64t u2 = fmul2(x01.x, w2[0]);
            u2 = ffma2(x01.y, w2[1], u2);
            u2 = ffma2(x23.x, w2[2], u2);
            u2 = ffma2(x23.y, w2[3], u2);
            u2 = ffma2(x45.x, w2[4], u2);
            u2 = ffma2(x45.y, w2[5], u2);
            u2 = ffma2(x67.x, w2[6], u2);
            u2 = ffma2(x67.y, w2[7], u2);
            s0a[bp] = fadd2(s0a[bp], u2);
            float f0, f1; upk2(u2, f0, f1);
            op[(size_t)(2 * bp) * (N_ * KDIM)]     = __float2half_rn(f0);
            op[(size_t)(2 * bp + 1) * (N_ * KDIM)] = __float2half_rn(f1);
        }
    }
#pragma unroll
    for (int bp = 0; bp < 8; bp++) {
        float f0, f1; upk2(s0a[bp], f0, f1);
        atomicAdd(&g_s[0][(b0 + 2 * bp) * KDIM + k],     0.1f * f0);
        atomicAdd(&g_s[0][(b0 + 2 * bp + 1) * KDIM + k], 0.1f * f1);
    }
}

// ---------------------------------------------------------------------------
// squash helper applied to one element owned by thread in an aligned 16-group
// ---------------------------------------------------------------------------
__device__ __forceinline__ float squash16(float val) {
    float sq = val * val;
    sq += __shfl_xor_sync(0xffffffffu, sq, 8);
    sq += __shfl_xor_sync(0xffffffffu, sq, 4);
    sq += __shfl_xor_sync(0xffffffffu, sq, 2);
    sq += __shfl_xor_sync(0xffffffffu, sq, 1);
    float nrm = sqrtf(sq);
    return sq / (1.0f + sq) / (nrm + 1e-7f) * val;
}

// ---------------------------------------------------------------------------
// Routing pass (squash fused into the prologue; no b-logit tensor).
// ROUND==1: logit p = u.v0       -> accumulate s1
// ROUND==2: logit p = u.(v0+v1)  -> accumulate s2
// grid (B, 4): 1152 n per block, 144 per warp (divisible by 6) -> 512 blocks
// = single full wave at 4 blocks/SM. 10-lane groups; each group processes
// TWO n per iteration (6 per warp-iter): 4 batched LDG.128 + two interleaved
// dot/exp/shfl-sum chains (ILP 2, MLP 4).
// ---------------------------------------------------------------------------
#define FULLM 0xffffffffu
template <int ROUND>
__global__ void __launch_bounds__(256, 4) k_route(const float* __restrict__ bias) {
    int b = blockIdx.x;
    int chunk = blockIdx.y;            // 0..3
    int t = threadIdx.x;

    __shared__ float vs[KDIM];         // v0 (round1) or v0+v1 (round2)
    if (t < KDIM) {
        float bval = bias[t];
        float v0 = squash16(g_s[0][b * KDIM + t] + bval);
        if (ROUND == 1) vs[t] = v0;
        else            vs[t] = v0 + squash16(g_s[1][b * KDIM + t] + bval);
    }
    __syncthreads();

    int warp = t >> 5;
    int lane = t & 31;
    int g = (lane >= 20) ? 2 : (lane >= 10 ? 1 : 0);
    int c = lane - g * 10;
    bool active = (lane < 30);

    __half2 vr2[8];
    float acc[L_];
#pragma unroll
    for (int q = 0; q < 8; q++)
        vr2[q] = active ? __floats2half2_rn(vs[c * L_ + 2 * q],
                                            vs[c * L_ + 2 * q + 1])
                        : __floats2half2_rn(0.f, 0.f);
#pragma unroll
    for (int l = 0; l < L_; l++) acc[l] = 0.0f;

    const int NPW = 144;               // n per warp, divisible by 6
    int base_n = chunk * 1152 + warp * NPW;
    const __half* ubase = g_uh + ((size_t)b * N_ + base_n) * KDIM + c * L_;

#pragma unroll 2
    for (int it = 0; it < NPW / 6; it++) {
        const __half* up0 = ubase + (size_t)(it * 6 + g) * KDIM;
        const __half* up1 = up0 + (size_t)3 * KDIM;
        uint4 z4 = make_uint4(0u, 0u, 0u, 0u);
        uint4 a0 = active ? *(const uint4*)up0       : z4;
        uint4 b0 = active ? *(const uint4*)(up0 + 8) : z4;
        uint4 a1 = active ? *(const uint4*)up1       : z4;
        uint4 b1 = active ? *(const uint4*)(up1 + 8) : z4;
        __half2 u0[8], u1[8];
        u0[0] = *(__half2*)&a0.x; u0[1] = *(__half2*)&a0.y;
        u0[2] = *(__half2*)&a0.z; u0[3] = *(__half2*)&a0.w;
        u0[4] = *(__half2*)&b0.x; u0[5] = *(__half2*)&b0.y;
        u0[6] = *(__half2*)&b0.z; u0[7] = *(__half2*)&b0.w;
        u1[0] = *(__half2*)&a1.x; u1[1] = *(__half2*)&a1.y;
        u1[2] = *(__half2*)&a1.z; u1[3] = *(__half2*)&a1.w;
        u1[4] = *(__half2*)&b1.x; u1[5] = *(__half2*)&b1.y;
        u1[6] = *(__half2*)&b1.z; u1[7] = *(__half2*)&b1.w;

        // two interleaved logit dots (half2)
        __half2 p20 = __hmul2(u0[0], vr2[0]);
        __half2 p21 = __hmul2(u1[0], vr2[0]);
#pragma unroll
        for (int q = 1; q < 8; q++) {
            p20 = __hfma2(u0[q], vr2[q], p20);
            p21 = __hfma2(u1[q], vr2[q], p21);
        }
        float p0 = __low2float(p20) + __high2float(p20);
        float p1 = __low2float(p21) + __high2float(p21);

        float e0 = active ? __expf(p0) : 0.0f;
        float e1 = active ? __expf(p1) : 0.0f;

        // interleaved sums over the 10-lane group (c = 0..9)
        float s0 = e0, s1 = e1, t0, t1;
        t0 = __shfl_sync(FULLM, s0, lane + 8);
        t1 = __shfl_sync(FULLM, s1, lane + 8);
        if (c < 2) { s0 += t0; s1 += t1; }
        t0 = __shfl_sync(FULLM, s0, lane + 4);
        t1 = __shfl_sync(FULLM, s1, lane + 4);
        if (c < 4) { s0 += t0; s1 += t1; }
        t0 = __shfl_sync(FULLM, s0, lane + 2);
        t1 = __shfl_sync(FULLM, s1, lane + 2);
        if (c < 2) { s0 += t0; s1 += t1; }
        t0 = __shfl_sync(FULLM, s0, lane + 1);
        t1 = __shfl_sync(FULLM, s1, lane + 1);
        if (c < 1) { s0 += t0; s1 += t1; }
        float se0 = __shfl_sync(FULLM, s0, g * 10);
        float se1 = __shfl_sync(FULLM, s1, g * 10);

        float w0 = __fdividef(e0, se0);
        float w1 = __fdividef(e1, se1);
#pragma unroll
        for (int q = 0; q < 8; q++) {
            float2 f0 = __half22float2(u0[q]);
            float2 f1 = __half22float2(u1[q]);
            acc[2 * q]     = fmaf(w0, f0.x, fmaf(w1, f1.x, acc[2 * q]));
            acc[2 * q + 1] = fmaf(w0, f0.y, fmaf(w1, f1.y, acc[2 * q + 1]));
        }
    }

    // combine the 3 groups (lane i, i+10, i+20 share capsule c=i)
#pragma unroll
    for (int l = 0; l < L_; l++) {
        float a1 = __shfl_sync(FULLM, acc[l], lane + 10);
        float a2 = __shfl_sync(FULLM, acc[l], lane + 20);
        if (lane < 10) acc[l] += a1 + a2;
    }
    if (lane < 10) {
#pragma unroll
        for (int l = 0; l < L_; l++)
            atomicAdd(&g_s[ROUND][b * KDIM + lane * L_ + l], acc[l]);
    }
}

// ---------------------------------------------------------------------------
// Final squash of s2 -> d_out
// ---------------------------------------------------------------------------
__global__ void __launch_bounds__(160) k_out(const float* __restrict__ bias,
                                             float* __restrict__ out) {
    int b = blockIdx.x, t = threadIdx.x;
    out[b * KDIM + t] = squash16(g_s[2][b * KDIM + t] + bias[t]);
}

// ---------------------------------------------------------------------------
extern "C" void kernel_launch(void* const* d_in, const int* in_sizes, int n_in,
                              void* d_out, int out_size) {
    const float* x    = (const float*)d_in[0];   // [128,12,12,32,8] = [B, N, 8]
    const float* W    = (const float*)d_in[1];   // [4608, 8, 160]
    const float* bias = (const float*)d_in[2];   // [10, 16]
    float* out = (float*)d_out;                  // [128, 10, 16]
    (void)in_sizes; (void)n_in; (void)out_size;

    k_zero<<<(3 * SROW + 255) / 256, 256>>>();
    k_u_s0<<<dim3(B_ / 16, N_ / 32), 160>>>(x, W);
    k_route<1><<<dim3(B_, 4), 256>>>(bias);
    k_route<2><<<dim3(B_, 4), 256>>>(bias);
    k_out<<<B_, 160>>>(bias, out);
}

// round 8
// speedup vs baseline: 1.0623x; 1.0623x over previous
#include <cuda_runtime.h>
#include <cuda_fp16.h>
#include <cstdint>

// Problem constants
#define B_   128
#define N_   4608
#define IL_  8
#define C_   10
#define L_   16
#define KDIM 160          // C_*L_
#define SROW (B_*KDIM)    // 20480

typedef unsigned long long u64t;

// packed f32x2 helpers (sm_103a FFMA2 path — PTX only, ptxas won't auto-fuse)
__device__ __forceinline__ u64t pk2(float lo, float hi) {
    u64t r; asm("mov.b64 %0,{%1,%2};" : "=l"(r) : "f"(lo), "f"(hi)); return r;
}
__device__ __forceinline__ void upk2(u64t v, float& lo, float& hi) {
    asm("mov.b64 {%0,%1},%2;" : "=f"(lo), "=f"(hi) : "l"(v));
}
__device__ __forceinline__ u64t ffma2(u64t a, u64t b, u64t c) {
    u64t d; asm("fma.rn.f32x2 %0,%1,%2,%3;" : "=l"(d) : "l"(a), "l"(b), "l"(c));
    return d;
}
__device__ __forceinline__ u64t fmul2(u64t a, u64t b) {
    u64t d; asm("mul.rn.f32x2 %0,%1,%2;" : "=l"(d) : "l"(a), "l"(b)); return d;
}
__device__ __forceinline__ u64t fadd2(u64t a, u64t b) {
    u64t d; asm("add.rn.f32x2 %0,%1,%2;" : "=l"(d) : "l"(a), "l"(b)); return d;
}

// Scratch (allocation-free rule: __device__ globals)
__device__ __half g_uh[(size_t)B_ * N_ * KDIM];   // 188 MB prediction tensor (fp16)
__device__ float  g_s[3][SROW];                   // s accumulators per round

// ---------------------------------------------------------------------------
// Zero the s accumulators (must happen every replay)
// ---------------------------------------------------------------------------
__global__ void k_zero() {
    int i = blockIdx.x * blockDim.x + threadIdx.x;
    if (i < 3 * SROW) ((float*)g_s)[i] = 0.0f;
}

// ---------------------------------------------------------------------------
// K1: u[b,n,k] = sum_j x[b,n,j] * W[n,j,k]  (fp32 via packed FFMA2, fp16
//     store) FUSED with s0[b,k] += 0.1 * sum_n u[b,n,k].
// grid (B/16, N/32), block 160: kp = t%80 owns k-pair (2kp, 2kp+1);
// ns = t/80 selects one of two n handled per inner step.
//   W operand: direct LDG.64 (W[j,2kp], W[j,2kp+1])  (8B-aligned, L2-resident)
//   x operand: smem pre-duplicated (x,x) u64, LDS.64 broadcast
//   output: one cvt.rn.f16x2 + one coalesced STG.32 per 2 elements
// Full fp32 accumulation -> u rounded to fp16 exactly once.
// ---------------------------------------------------------------------------
__global__ void __launch_bounds__(160) k_u_s0(const float* __restrict__ x,
                                              const float* __restrict__ W) {
    int b0 = blockIdx.x * 16;
    int n0 = blockIdx.y * 32;
    int t = threadIdx.x;
    int kp = t % 80;            // k-pair index
    int ns = t / 80;            // n slot (0/1)
    __shared__ u64t xs[32 * 16 * IL_];   // 32 KB, [nn][bi][j] = (x,x) pairs

    for (int idx = t; idx < 32 * 16 * IL_; idx += 160) {
        int nn = idx >> 7, r = idx & 127;     // r = bi*8 + j
        int bi = r >> 3, j = r & 7;
        float val = x[(size_t)(b0 + bi) * (N_ * IL_) + (size_t)(n0 + nn) * IL_ + j];
        xs[(nn * 16 + bi) * IL_ + j] = pk2(val, val);
    }
    __syncthreads();

    u64t s0a[16];
#pragma unroll
    for (int i = 0; i < 16; i++) s0a[i] = pk2(0.f, 0.f);

    for (int nj2 = 0; nj2 < 16; nj2++) {
        int nn = nj2 * 2 + ns;                 // this thread's n within tile
        const float* Wn = W + (size_t)(n0 + nn) * (IL_ * KDIM) + 2 * kp;
        u64t w2[IL_];
#pragma unroll
        for (int j = 0; j < IL_; j++)
            w2[j] = *(const u64t*)(Wn + j * KDIM);
        __half2* op = (__half2*)(g_uh + ((size_t)b0 * N_ + (n0 + nn)) * KDIM
                                 + 2 * kp);
        const u64t* xp = &xs[nn * 16 * IL_];
#pragma unroll
        for (int bi = 0; bi < 16; bi++) {
            const u64t* xb = xp + bi * IL_;
            u64t u2 = fmul2(xb[0], w2[0]);
#pragma unroll
            for (int j = 1; j < IL_; j++) u2 = ffma2(xb[j], w2[j], u2);
            s0a[bi] = fadd2(s0a[bi], u2);
            float f0, f1; upk2(u2, f0, f1);
            op[(size_t)bi * (N_ * KDIM / 2)] = __floats2half2_rn(f0, f1);
        }
    }
#pragma unroll
    for (int bi = 0; bi < 16; bi++) {
        float f0, f1; upk2(s0a[bi], f0, f1);
        atomicAdd(&g_s[0][(b0 + bi) * KDIM + 2 * kp],     0.1f * f0);
        atomicAdd(&g_s[0][(b0 + bi) * KDIM + 2 * kp + 1], 0.1f * f1);
    }
}

// ---------------------------------------------------------------------------
// squash helper applied to one element owned by thread in an aligned 16-group
// ---------------------------------------------------------------------------
__device__ __forceinline__ float squash16(float val) {
    float sq = val * val;
    sq += __shfl_xor_sync(0xffffffffu, sq, 8);
    sq += __shfl_xor_sync(0xffffffffu, sq, 4);
    sq += __shfl_xor_sync(0xffffffffu, sq, 2);
    sq += __shfl_xor_sync(0xffffffffu, sq, 1);
    float nrm = sqrtf(sq);
    return sq / (1.0f + sq) / (nrm + 1e-7f) * val;
}

// ---------------------------------------------------------------------------
// Routing pass (squash fused into the prologue; no b-logit tensor).
// ROUND==1: logit p = u.v0       -> accumulate s1
// ROUND==2: logit p = u.(v0+v1)  -> accumulate s2
// grid (B, 4): 1152 n per block, 144 per warp (divisible by 6) -> 512 blocks
// = single full wave at 4 blocks/SM. 10-lane groups; each group processes
// TWO n per iteration (6 per warp-iter): 4 batched LDG.128 + two interleaved
// dot/exp/shfl-sum chains (ILP 2, MLP 4).
// ---------------------------------------------------------------------------
#define FULLM 0xffffffffu
template <int ROUND>
__global__ void __launch_bounds__(256, 4) k_route(const float* __restrict__ bias) {
    int b = blockIdx.x;
    int chunk = blockIdx.y;            // 0..3
    int t = threadIdx.x;

    __shared__ float vs[KDIM];         // v0 (round1) or v0+v1 (round2)
    if (t < KDIM) {
        float bval = bias[t];
        float v0 = squash16(g_s[0][b * KDIM + t] + bval);
        if (ROUND == 1) vs[t] = v0;
        else            vs[t] = v0 + squash16(g_s[1][b * KDIM + t] + bval);
    }
    __syncthreads();

    int warp = t >> 5;
    int lane = t & 31;
    int g = (lane >= 20) ? 2 : (lane >= 10 ? 1 : 0);
    int c = lane - g * 10;
    bool active = (lane < 30);

    __half2 vr2[8];
    float acc[L_];
#pragma unroll
    for (int q = 0; q < 8; q++)
        vr2[q] = active ? __floats2half2_rn(vs[c * L_ + 2 * q],
                                            vs[c * L_ + 2 * q + 1])
                        : __floats2half2_rn(0.f, 0.f);
#pragma unroll
    for (int l = 0; l < L_; l++) acc[l] = 0.0f;

    const int NPW = 144;               // n per warp, divisible by 6
    int base_n = chunk * 1152 + warp * NPW;
    const __half* ubase = g_uh + ((size_t)b * N_ + base_n) * KDIM + c * L_;

#pragma unroll 2
    for (int it = 0; it < NPW / 6; it++) {
        const __half* up0 = ubase + (size_t)(it * 6 + g) * KDIM;
        const __half* up1 = up0 + (size_t)3 * KDIM;
        uint4 z4 = make_uint4(0u, 0u, 0u, 0u);
        uint4 a0 = active ? *(const uint4*)up0       : z4;
        uint4 b0 = active ? *(const uint4*)(up0 + 8) : z4;
        uint4 a1 = active ? *(const uint4*)up1       : z4;
        uint4 b1 = active ? *(const uint4*)(up1 + 8) : z4;
        __half2 u0[8], u1[8];
        u0[0] = *(__half2*)&a0.x; u0[1] = *(__half2*)&a0.y;
        u0[2] = *(__half2*)&a0.z; u0[3] = *(__half2*)&a0.w;
        u0[4] = *(__half2*)&b0.x; u0[5] = *(__half2*)&b0.y;
        u0[6] = *(__half2*)&b0.z; u0[7] = *(__half2*)&b0.w;
        u1[0] = *(__half2*)&a1.x; u1[1] = *(__half2*)&a1.y;
        u1[2] = *(__half2*)&a1.z; u1[3] = *(__half2*)&a1.w;
        u1[4] = *(__half2*)&b1.x; u1[5] = *(__half2*)&b1.y;
        u1[6] = *(__half2*)&b1.z; u1[7] = *(__half2*)&b1.w;

        // two interleaved logit dots (half2)
        __half2 p20 = __hmul2(u0[0], vr2[0]);
        __half2 p21 = __hmul2(u1[0], vr2[0]);
#pragma unroll
        for (int q = 1; q < 8; q++) {
            p20 = __hfma2(u0[q], vr2[q], p20);
            p21 = __hfma2(u1[q], vr2[q], p21);
        }
        float p0 = __low2float(p20) + __high2float(p20);
        float p1 = __low2float(p21) + __high2float(p21);

        float e0 = active ? __expf(p0) : 0.0f;
        float e1 = active ? __expf(p1) : 0.0f;

        // interleaved sums over the 10-lane group (c = 0..9)
        float s0 = e0, s1 = e1, t0, t1;
        t0 = __shfl_sync(FULLM, s0, lane + 8);
        t1 = __shfl_sync(FULLM, s1, lane + 8);
        if (c < 2) { s0 += t0; s1 += t1; }
        t0 = __shfl_sync(FULLM, s0, lane + 4);
        t1 = __shfl_sync(FULLM, s1, lane + 4);
        if (c < 4) { s0 += t0; s1 += t1; }
        t0 = __shfl_sync(FULLM, s0, lane + 2);
        t1 = __shfl_sync(FULLM, s1, lane + 2);
        if (c < 2) { s0 += t0; s1 += t1; }
        t0 = __shfl_sync(FULLM, s0, lane + 1);
        t1 = __shfl_sync(FULLM, s1, lane + 1);
        if (c < 1) { s0 += t0; s1 += t1; }
        float se0 = __shfl_sync(FULLM, s0, g * 10);
        float se1 = __shfl_sync(FULLM, s1, g * 10);

        float w0 = __fdividef(e0, se0);
        float w1 = __fdividef(e1, se1);
#pragma unroll
        for (int q = 0; q < 8; q++) {
            float2 f0 = __half22float2(u0[q]);
            float2 f1 = __half22float2(u1[q]);
            acc[2 * q]     = fmaf(w0, f0.x, fmaf(w1, f1.x, acc[2 * q]));
            acc[2 * q + 1] = fmaf(w0, f0.y, fmaf(w1, f1.y, acc[2 * q + 1]));
        }
    }

    // combine the 3 groups (lane i, i+10, i+20 share capsule c=i)
#pragma unroll
    for (int l = 0; l < L_; l++) {
        float a1 = __shfl_sync(FULLM, acc[l], lane + 10);
        float a2 = __shfl_sync(FULLM, acc[l], lane + 20);
        if (lane < 10) acc[l] += a1 + a2;
    }
    if (lane < 10) {
#pragma unroll
        for (int l = 0; l < L_; l++)
            atomicAdd(&g_s[ROUND][b * KDIM + lane * L_ + l], acc[l]);
    }
}

// ---------------------------------------------------------------------------
// Final squash of s2 -> d_out
// ---------------------------------------------------------------------------
__global__ void __launch_bounds__(160) k_out(const float* __restrict__ bias,
                                             float* __restrict__ out) {
    int b = blockIdx.x, t = threadIdx.x;
    out[b * KDIM + t] = squash16(g_s[2][b * KDIM + t] + bias[t]);
}

// ---------------------------------------------------------------------------
extern "C" void kernel_launch(void* const* d_in, const int* in_sizes, int n_in,
                              void* d_out, int out_size) {
    const float* x    = (const float*)d_in[0];   // [128,12,12,32,8] = [B, N, 8]
    const float* W    = (const float*)d_in[1];   // [4608, 8, 160]
    const float* bias = (const float*)d_in[2];   // [10, 16]
    float* out = (float*)d_out;                  // [128, 10, 16]
    (void)in_sizes; (void)n_in; (void)out_size;

    k_zero<<<(3 * SROW + 255) / 256, 256>>>();
    k_u_s0<<<dim3(B_ / 16, N_ / 32), 160>>>(x, W);
    k_route<1><<<dim3(B_, 4), 256>>>(bias);
    k_route<2><<<dim3(B_, 4), 256>>>(bias);
    k_out<<<B_, 160>>>(bias, out);
}

// round 9
// speedup vs baseline: 1.0777x; 1.0146x over previous
#include <cuda_runtime.h>
#include <cuda_fp16.h>
#include <cstdint>

// Problem constants
#define B_   128
#define N_   4608
#define IL_  8
#define C_   10
#define L_   16
#define KDIM 160          // C_*L_
#define SROW (B_*KDIM)    // 20480

typedef unsigned long long u64t;

// packed f32x2 helpers (sm_103a FFMA2 path — PTX only, ptxas won't auto-fuse)
__device__ __forceinline__ u64t pk2(float lo, float hi) {
    u64t r; asm("mov.b64 %0,{%1,%2};" : "=l"(r) : "f"(lo), "f"(hi)); return r;
}
__device__ __forceinline__ void upk2(u64t v, float& lo, float& hi) {
    asm("mov.b64 {%0,%1},%2;" : "=f"(lo), "=f"(hi) : "l"(v));
}
__device__ __forceinline__ u64t ffma2(u64t a, u64t b, u64t c) {
    u64t d; asm("fma.rn.f32x2 %0,%1,%2,%3;" : "=l"(d) : "l"(a), "l"(b), "l"(c));
    return d;
}
__device__ __forceinline__ u64t fmul2(u64t a, u64t b) {
    u64t d; asm("mul.rn.f32x2 %0,%1,%2;" : "=l"(d) : "l"(a), "l"(b)); return d;
}
__device__ __forceinline__ u64t fadd2(u64t a, u64t b) {
    u64t d; asm("add.rn.f32x2 %0,%1,%2;" : "=l"(d) : "l"(a), "l"(b)); return d;
}

// Scratch (allocation-free rule: __device__ globals)
__device__ __half g_uh[(size_t)B_ * N_ * KDIM];   // 188 MB prediction tensor (fp16)
__device__ float  g_s[3][SROW];                   // s accumulators per round

// ---------------------------------------------------------------------------
// Zero the s accumulators (must happen every replay)
// ---------------------------------------------------------------------------
__global__ void k_zero() {
    int i = blockIdx.x * blockDim.x + threadIdx.x;
    if (i < 3 * SROW) ((float*)g_s)[i] = 0.0f;
}

// ---------------------------------------------------------------------------
// K1: u[b,n,k] = sum_j x[b,n,j] * W[n,j,k]  (fp32 via packed FFMA2, fp16
//     store) FUSED with s0[b,k] += 0.1 * sum_n u[b,n,k].  (unchanged R8)
// ---------------------------------------------------------------------------
__global__ void __launch_bounds__(160) k_u_s0(const float* __restrict__ x,
                                              const float* __restrict__ W) {
    int b0 = blockIdx.x * 16;
    int n0 = blockIdx.y * 32;
    int t = threadIdx.x;
    int kp = t % 80;            // k-pair index
    int ns = t / 80;            // n slot (0/1)
    __shared__ u64t xs[32 * 16 * IL_];   // 32 KB, [nn][bi][j] = (x,x) pairs

    for (int idx = t; idx < 32 * 16 * IL_; idx += 160) {
        int nn = idx >> 7, r = idx & 127;     // r = bi*8 + j
        int bi = r >> 3, j = r & 7;
        float val = x[(size_t)(b0 + bi) * (N_ * IL_) + (size_t)(n0 + nn) * IL_ + j];
        xs[(nn * 16 + bi) * IL_ + j] = pk2(val, val);
    }
    __syncthreads();

    u64t s0a[16];
#pragma unroll
    for (int i = 0; i < 16; i++) s0a[i] = pk2(0.f, 0.f);

    for (int nj2 = 0; nj2 < 16; nj2++) {
        int nn = nj2 * 2 + ns;                 // this thread's n within tile
        const float* Wn = W + (size_t)(n0 + nn) * (IL_ * KDIM) + 2 * kp;
        u64t w2[IL_];
#pragma unroll
        for (int j = 0; j < IL_; j++)
            w2[j] = *(const u64t*)(Wn + j * KDIM);
        __half2* op = (__half2*)(g_uh + ((size_t)b0 * N_ + (n0 + nn)) * KDIM
                                 + 2 * kp);
        const u64t* xp = &xs[nn * 16 * IL_];
#pragma unroll
        for (int bi = 0; bi < 16; bi++) {
            const u64t* xb = xp + bi * IL_;
            u64t u2 = fmul2(xb[0], w2[0]);
#pragma unroll
            for (int j = 1; j < IL_; j++) u2 = ffma2(xb[j], w2[j], u2);
            s0a[bi] = fadd2(s0a[bi], u2);
            float f0, f1; upk2(u2, f0, f1);
            op[(size_t)bi * (N_ * KDIM / 2)] = __floats2half2_rn(f0, f1);
        }
    }
#pragma unroll
    for (int bi = 0; bi < 16; bi++) {
        float f0, f1; upk2(s0a[bi], f0, f1);
        atomicAdd(&g_s[0][(b0 + bi) * KDIM + 2 * kp],     0.1f * f0);
        atomicAdd(&g_s[0][(b0 + bi) * KDIM + 2 * kp + 1], 0.1f * f1);
    }
}

// ---------------------------------------------------------------------------
// squash helper applied to one element owned by thread in an aligned 16-group
// ---------------------------------------------------------------------------
__device__ __forceinline__ float squash16(float val) {
    float sq = val * val;
    sq += __shfl_xor_sync(0xffffffffu, sq, 8);
    sq += __shfl_xor_sync(0xffffffffu, sq, 4);
    sq += __shfl_xor_sync(0xffffffffu, sq, 2);
    sq += __shfl_xor_sync(0xffffffffu, sq, 1);
    float nrm = sqrtf(sq);
    return sq / (1.0f + sq) / (nrm + 1e-7f) * val;
}

// ---------------------------------------------------------------------------
// Routing pass (squash fused into prologue; no b-logit tensor).
// ROUND==1: logit p = u.v0       -> accumulate s1
// ROUND==2: logit p = u.(v0+v1)  -> accumulate s2
// grid (B, 4): 1152 n/block, 144 per warp = 16 iters x 9 n.
// 10-lane groups; each group handles THREE n per iteration (stride 3):
// 6 batched LDG.128 (MLP 6) + three interleaved dot/exp/shfl chains (ILP 3).
// Accumulators in packed f32x2 (FFMA2).
// ---------------------------------------------------------------------------
#define FULLM 0xffffffffu
template <int ROUND>
__global__ void __launch_bounds__(256, 4) k_route(const float* __restrict__ bias) {
    int b = blockIdx.x;
    int chunk = blockIdx.y;            // 0..3
    int t = threadIdx.x;

    __shared__ float vs[KDIM];         // v0 (round1) or v0+v1 (round2)
    if (t < KDIM) {
        float bval = bias[t];
        float v0 = squash16(g_s[0][b * KDIM + t] + bval);
        if (ROUND == 1) vs[t] = v0;
        else            vs[t] = v0 + squash16(g_s[1][b * KDIM + t] + bval);
    }
    __syncthreads();

    int warp = t >> 5;
    int lane = t & 31;
    int g = (lane >= 20) ? 2 : (lane >= 10 ? 1 : 0);
    int c = lane - g * 10;
    bool active = (lane < 30);

    __half2 vr2[8];
    u64t acc2[8];
#pragma unroll
    for (int q = 0; q < 8; q++) {
        vr2[q] = active ? __floats2half2_rn(vs[c * L_ + 2 * q],
                                            vs[c * L_ + 2 * q + 1])
                        : __floats2half2_rn(0.f, 0.f);
        acc2[q] = pk2(0.f, 0.f);
    }

    const int NPW = 144;               // n per warp = 16 iters x 9
    int base_n = chunk * 1152 + warp * NPW;
    const __half* ubase = g_uh + ((size_t)b * N_ + base_n) * KDIM + c * L_;

    for (int it = 0; it < 16; it++) {
        // group g owns n-offsets it*9 + {g, 3+g, 6+g}
        const __half* up0 = ubase + (size_t)(it * 9 + g) * KDIM;
        const __half* up1 = up0 + (size_t)3 * KDIM;
        const __half* up2 = up0 + (size_t)6 * KDIM;
        uint4 z4 = make_uint4(0u, 0u, 0u, 0u);
        uint4 a0 = active ? *(const uint4*)up0       : z4;
        uint4 d0 = active ? *(const uint4*)(up0 + 8) : z4;
        uint4 a1 = active ? *(const uint4*)up1       : z4;
        uint4 d1 = active ? *(const uint4*)(up1 + 8) : z4;
        uint4 a2 = active ? *(const uint4*)up2       : z4;
        uint4 d2 = active ? *(const uint4*)(up2 + 8) : z4;

        const __half2* u0 = (const __half2*)&a0;   // [0..3]=a0, then d0
        const __half2* e0p = (const __half2*)&d0;
        const __half2* u1 = (const __half2*)&a1;
        const __half2* e1p = (const __half2*)&d1;
        const __half2* u2p = (const __half2*)&a2;
        const __half2* e2p = (const __half2*)&d2;

        // three interleaved logit dots (half2)
        __half2 p20 = __hmul2(u0[0], vr2[0]);
        __half2 p21 = __hmul2(u1[0], vr2[0]);
        __half2 p22 = __hmul2(u2p[0], vr2[0]);
#pragma unroll
        for (int q = 1; q < 4; q++) {
            p20 = __hfma2(u0[q], vr2[q], p20);
            p21 = __hfma2(u1[q], vr2[q], p21);
            p22 = __hfma2(u2p[q], vr2[q], p22);
        }
#pragma unroll
        for (int q = 0; q < 4; q++) {
            p20 = __hfma2(e0p[q], vr2[4 + q], p20);
            p21 = __hfma2(e1p[q], vr2[4 + q], p21);
            p22 = __hfma2(e2p[q], vr2[4 + q], p22);
        }
        float p0 = __low2float(p20) + __high2float(p20);
        float p1 = __low2float(p21) + __high2float(p21);
        float p2 = __low2float(p22) + __high2float(p22);

        float e0 = active ? __expf(p0) : 0.0f;
        float e1 = active ? __expf(p1) : 0.0f;
        float e2 = active ? __expf(p2) : 0.0f;

        // interleaved sums over the 10-lane group (c = 0..9)
        float s0 = e0, s1 = e1, s2 = e2, t0, t1, t2;
        t0 = __shfl_sync(FULLM, s0, lane + 8);
        t1 = __shfl_sync(FULLM, s1, lane + 8);
        t2 = __shfl_sync(FULLM, s2, lane + 8);
        if (c < 2) { s0 += t0; s1 += t1; s2 += t2; }
        t0 = __shfl_sync(FULLM, s0, lane + 4);
        t1 = __shfl_sync(FULLM, s1, lane + 4);
        t2 = __shfl_sync(FULLM, s2, lane + 4);
        if (c < 4) { s0 += t0; s1 += t1; s2 += t2; }
        t0 = __shfl_sync(FULLM, s0, lane + 2);
        t1 = __shfl_sync(FULLM, s1, lane + 2);
        t2 = __shfl_sync(FULLM, s2, lane + 2);
        if (c < 2) { s0 += t0; s1 += t1; s2 += t2; }
        t0 = __shfl_sync(FULLM, s0, lane + 1);
        t1 = __shfl_sync(FULLM, s1, lane + 1);
        t2 = __shfl_sync(FULLM, s2, lane + 1);
        if (c < 1) { s0 += t0; s1 += t1; s2 += t2; }
        float se0 = __shfl_sync(FULLM, s0, g * 10);
        float se1 = __shfl_sync(FULLM, s1, g * 10);
        float se2 = __shfl_sync(FULLM, s2, g * 10);

        u64t w0 = pk2(__fdividef(e0, se0), __fdividef(e0, se0));
        u64t w1 = pk2(__fdividef(e1, se1), __fdividef(e1, se1));
        u64t w2 = pk2(__fdividef(e2, se2), __fdividef(e2, se2));
#pragma unroll
        for (int q = 0; q < 4; q++) {
            float2 f;
            f = __half22float2(u0[q]);  acc2[q]     = ffma2(pk2(f.x, f.y), w0, acc2[q]);
            f = __half22float2(e0p[q]); acc2[4 + q] = ffma2(pk2(f.x, f.y), w0, acc2[4 + q]);
            f = __half22float2(u1[q]);  acc2[q]     = ffma2(pk2(f.x, f.y), w1, acc2[q]);
            f = __half22float2(e1p[q]); acc2[4 + q] = ffma2(pk2(f.x, f.y), w1, acc2[4 + q]);
            f = __half22float2(u2p[q]); acc2[q]     = ffma2(pk2(f.x, f.y), w2, acc2[q]);
            f = __half22float2(e2p[q]); acc2[4 + q] = ffma2(pk2(f.x, f.y), w2, acc2[4 + q]);
        }
    }

    // unpack and combine the 3 groups (lane i, i+10, i+20 share capsule c=i)
    float acc[L_];
#pragma unroll
    for (int q = 0; q < 8; q++) upk2(acc2[q], acc[2 * q], acc[2 * q + 1]);
#pragma unroll
    for (int l = 0; l < L_; l++) {
        float a1 = __shfl_sync(FULLM, acc[l], lane + 10);
        float a2 = __shfl_sync(FULLM, acc[l], lane + 20);
        if (lane < 10) acc[l] += a1 + a2;
    }
    if (lane < 10) {
#pragma unroll
        for (int l = 0; l < L_; l++)
            atomicAdd(&g_s[ROUND][b * KDIM + lane * L_ + l], acc[l]);
    }
}

// ---------------------------------------------------------------------------
// Final squash of s2 -> d_out
// ---------------------------------------------------------------------------
__global__ void __launch_bounds__(160) k_out(const float* __restrict__ bias,
                                             float* __restrict__ out) {
    int b = blockIdx.x, t = threadIdx.x;
    out[b * KDIM + t] = squash16(g_s[2][b * KDIM + t] + bias[t]);
}

// ---------------------------------------------------------------------------
extern "C" void kernel_launch(void* const* d_in, const int* in_sizes, int n_in,
                              void* d_out, int out_size) {
    const float* x    = (const float*)d_in[0];   // [128,12,12,32,8] = [B, N, 8]
    const float* W    = (const float*)d_in[1];   // [4608, 8, 160]
    const float* bias = (const float*)d_in[2];   // [10, 16]
    float* out = (float*)d_out;                  // [128, 10, 16]
    (void)in_sizes; (void)n_in; (void)out_size;

    k_zero<<<(3 * SROW + 255) / 256, 256>>>();
    k_u_s0<<<dim3(B_ / 16, N_ / 32), 160>>>(x, W);
    k_route<1><<<dim3(B_, 4), 256>>>(bias);
    k_route<2><<<dim3(B_, 4), 256>>>(bias);
    k_out<<<B_, 160>>>(bias, out);
}